// round 2
// baseline (speedup 1.0000x reference)
#include <cuda_runtime.h>
#include <math.h>

#define NN 100000
#define NEG_SLOPE 0.2f

// ---------------- scratch (device globals; no allocations allowed) ----------
__device__ float    g_h1[NN * 64];      // layer1 features [N, 2, 32]
__device__ float    g_as1[NN * 2];
__device__ float    g_ad1[NN * 2];
__device__ unsigned g_emax1[NN * 2];    // encoded float max
__device__ float    g_den1[NN * 2];
__device__ float    g_agg1[NN * 64];

__device__ float    g_hin2[NN * 32];    // relu(mean-heads + b1)
__device__ float    g_h2[NN * 32];
__device__ float    g_as2[NN];
__device__ float    g_ad2[NN];
__device__ unsigned g_emax2[NN];
__device__ float    g_den2[NN];
__device__ float    g_agg2[NN * 32];

__device__ float    g_imp[NN];
__device__ int      g_idx64;            // 1 if edge_index is int64, 0 if int32

// ------------- order-preserving float <-> unsigned encoding for atomicMax ---
__device__ __forceinline__ unsigned enc_f(float f) {
    unsigned b = __float_as_uint(f);
    return b ^ ((unsigned)((int)b >> 31) | 0x80000000u);
}
__device__ __forceinline__ float dec_f(unsigned u) {
    unsigned b = (u & 0x80000000u) ? (u ^ 0x80000000u) : ~u;
    return __uint_as_float(b);
}

__device__ __forceinline__ float lrelu(float x) {
    return x > 0.f ? x : NEG_SLOPE * x;
}

// vectorized global reduction (sm_90+)
__device__ __forceinline__ void red_add_v4(float* addr, float a, float b, float c, float d) {
    asm volatile("red.global.add.v4.f32 [%0], {%1,%2,%3,%4};"
                 :: "l"(addr), "f"(a), "f"(b), "f"(c), "f"(d) : "memory");
}

// ------------------------- edge-index dtype detection -----------------------
__global__ void detect_kernel(const int* __restrict__ ei32, int nwords) {
    // If underlying dtype is int64 (values < 2^31), every odd 32-bit word is 0.
    int odd_nonzero = 0;
    int cnt = nwords < 512 ? nwords / 2 : 256;
    for (int i = threadIdx.x; i < cnt; i += 32)
        if (ei32[2 * i + 1] != 0) odd_nonzero = 1;
    odd_nonzero = __any_sync(0xFFFFFFFFu, odd_nonzero);
    if (threadIdx.x == 0) g_idx64 = odd_nonzero ? 0 : 1;
}

__device__ __forceinline__ void load_sd(const void* ei, int E, int i, int idx64,
                                        int& s, int& d) {
    if (idx64) {
        const long long* p = (const long long*)ei;
        s = (int)p[i]; d = (int)p[E + i];
    } else {
        const int* p = (const int*)ei;
        s = p[i]; d = p[E + i];
    }
}

// --------------------- fused GEMM + attention coefficients ------------------
template<int IN, int H>
__global__ void gemm_att_kernel(const float* __restrict__ x,
                                const float* __restrict__ W,
                                const float* __restrict__ att_src,
                                const float* __restrict__ att_dst,
                                float* __restrict__ hout,
                                float* __restrict__ asrc,
                                float* __restrict__ adst,
                                int N) {
    constexpr int COLS  = H * 32;
    constexpr int RPI   = 256 / COLS;   // rows per iteration
    constexpr int ITERS = 16;

    __shared__ float Ws[IN * COLS];
    __shared__ float as_s[COLS];
    __shared__ float ad_s[COLS];
    __shared__ float xs[RPI][IN];

    int t = threadIdx.x;
    for (int i = t; i < IN * COLS; i += 256) Ws[i] = W[i];
    if (t < COLS) { as_s[t] = att_src[t]; ad_s[t] = att_dst[t]; }
    __syncthreads();

    int col  = t % COLS;
    int r    = t / COLS;
    int lane = t & 31;
    int head = col >> 5;
    long long row0 = (long long)blockIdx.x * (RPI * ITERS);

    for (int it = 0; it < ITERS; ++it) {
        long long rowbase = row0 + (long long)it * RPI;
        __syncthreads();
        for (int i = t; i < RPI * IN; i += 256) {
            int rr = i / IN, k = i % IN;
            long long row = rowbase + rr;
            xs[rr][k] = (row < N) ? x[row * IN + k] : 0.f;
        }
        __syncthreads();

        long long row = rowbase + r;
        float acc = 0.f;
        #pragma unroll
        for (int k = 0; k < IN; ++k) acc += xs[r][k] * Ws[k * COLS + col];

        float s1 = acc * as_s[col];
        float s2 = acc * ad_s[col];
        #pragma unroll
        for (int o = 16; o > 0; o >>= 1) {
            s1 += __shfl_xor_sync(0xFFFFFFFFu, s1, o);
            s2 += __shfl_xor_sync(0xFFFFFFFFu, s2, o);
        }
        if (row < N) {
            hout[row * COLS + col] = acc;
            if (lane == 0) {
                asrc[row * H + head] = s1;
                adst[row * H + head] = s2;
            }
        }
    }
}

// ------------------------------ edge passes --------------------------------
template<int H>
__global__ void edge_max_kernel(const void* __restrict__ ei, int E, int N,
                                const float* __restrict__ asrc,
                                const float* __restrict__ adst,
                                unsigned* __restrict__ emax) {
    int i = blockIdx.x * blockDim.x + threadIdx.x;
    int Etot = E + N;
    if (i >= Etot) return;
    int idx64 = g_idx64;
    int s, d;
    if (i < E) load_sd(ei, E, i, idx64, s, d); else s = d = i - E;
    #pragma unroll
    for (int h = 0; h < H; ++h) {
        float e = lrelu(asrc[s * H + h] + adst[d * H + h]);
        atomicMax(&emax[d * H + h], enc_f(e));
    }
}

template<int H>
__global__ void edge_sum_kernel(const void* __restrict__ ei, int E, int N,
                                const float* __restrict__ asrc,
                                const float* __restrict__ adst,
                                const unsigned* __restrict__ emax,
                                float* __restrict__ denom) {
    int i = blockIdx.x * blockDim.x + threadIdx.x;
    int Etot = E + N;
    if (i >= Etot) return;
    int idx64 = g_idx64;
    int s, d;
    if (i < E) load_sd(ei, E, i, idx64, s, d); else s = d = i - E;
    #pragma unroll
    for (int h = 0; h < H; ++h) {
        float e  = lrelu(asrc[s * H + h] + adst[d * H + h]);
        float ex = expf(e - dec_f(emax[d * H + h]));
        atomicAdd(&denom[d * H + h], ex);
    }
}

template<int H>
__global__ void edge_agg_kernel(const void* __restrict__ ei, int E, int N,
                                const float* __restrict__ asrc,
                                const float* __restrict__ adst,
                                const unsigned* __restrict__ emax,
                                const float* __restrict__ denom,
                                const float* __restrict__ hfeat,
                                float* __restrict__ agg) {
    int i = blockIdx.x * blockDim.x + threadIdx.x;
    int Etot = E + N;
    if (i >= Etot) return;
    int idx64 = g_idx64;
    int s, d;
    if (i < E) load_sd(ei, E, i, idx64, s, d); else s = d = i - E;
    #pragma unroll
    for (int h = 0; h < H; ++h) {
        float e     = lrelu(asrc[s * H + h] + adst[d * H + h]);
        float ex    = expf(e - dec_f(emax[d * H + h]));
        float alpha = ex / (denom[d * H + h] + 1e-16f);
        const float4* hs = reinterpret_cast<const float4*>(hfeat + ((size_t)s * H + h) * 32);
        float* op = agg + ((size_t)d * H + h) * 32;
        #pragma unroll
        for (int j = 0; j < 8; ++j) {
            float4 v = hs[j];
            red_add_v4(op + 4 * j, alpha * v.x, alpha * v.y, alpha * v.z, alpha * v.w);
        }
    }
}

// --------------------------- layer finalization -----------------------------
__global__ void finalize1_kernel(const float* __restrict__ agg,
                                 const float* __restrict__ b,
                                 float* __restrict__ out, int N) {
    int i = blockIdx.x * blockDim.x + threadIdx.x;
    if (i >= N * 32) return;
    int n = i >> 5, d = i & 31;
    float v = 0.5f * (agg[n * 64 + d] + agg[n * 64 + 32 + d]) + b[d];
    out[i] = v > 0.f ? v : 0.f;
}

__global__ void finalize2_kernel(const float* __restrict__ agg,
                                 const float* __restrict__ b,
                                 float* __restrict__ embeds,
                                 float* __restrict__ imp_out,  // may be null
                                 float* __restrict__ imp_scratch,
                                 int N) {
    int n = blockIdx.x * blockDim.x + threadIdx.x;
    if (n >= N) return;
    float ss = 0.f;
    #pragma unroll
    for (int d = 0; d < 32; ++d) {
        float v = agg[n * 32 + d] + b[d];
        embeds[n * 32 + d] = v;
        ss += v * v;
    }
    float nm = sqrtf(ss);
    imp_scratch[n] = nm;
    if (imp_out) imp_out[n] = nm;
}

// --------------------------------- top-k ------------------------------------
__global__ void topk_kernel(const float* __restrict__ imp, int N,
                            float* __restrict__ out_idx /* 5 floats */) {
    __shared__ float bv[256];
    __shared__ int   bi[256];
    __shared__ int   chosen[5];
    for (int r = 0; r < 5; ++r) {
        float best = -1e30f; int besti = 0x7FFFFFFF;
        for (int i = threadIdx.x; i < N; i += 256) {
            bool skip = false;
            for (int c = 0; c < r; ++c) if (chosen[c] == i) skip = true;
            if (skip) continue;
            float v = imp[i];
            if (v > best || (v == best && i < besti)) { best = v; besti = i; }
        }
        bv[threadIdx.x] = best;
        bi[threadIdx.x] = besti;
        __syncthreads();
        if (threadIdx.x == 0) {
            float B = -1e30f; int BI = 0x7FFFFFFF;
            for (int t = 0; t < 256; ++t) {
                if (bv[t] > B || (bv[t] == B && bi[t] < BI)) { B = bv[t]; BI = bi[t]; }
            }
            chosen[r] = BI;
            if (out_idx) out_idx[r] = (float)BI;
        }
        __syncthreads();
    }
}

// --------------------------------- launch -----------------------------------
extern "C" void kernel_launch(void* const* d_in, const int* in_sizes, int n_in,
                              void* d_out, int out_size) {
    const float* x    = (const float*)d_in[0];
    const void*  ei   = d_in[1];
    const float* W1   = (const float*)d_in[2];
    const float* as1w = (const float*)d_in[3];
    const float* ad1w = (const float*)d_in[4];
    const float* b1   = (const float*)d_in[5];
    const float* W2   = (const float*)d_in[6];
    const float* as2w = (const float*)d_in[7];
    const float* ad2w = (const float*)d_in[8];
    const float* b2   = (const float*)d_in[9];
    float* out = (float*)d_out;

    int N = in_sizes[0] / 64;
    int E = in_sizes[1] / 2;
    if (N > NN) N = NN;

    float *p_h1, *p_as1, *p_ad1, *p_den1, *p_agg1, *p_hin2, *p_h2;
    float *p_as2, *p_ad2, *p_den2, *p_agg2, *p_imp;
    unsigned *p_emax1, *p_emax2;
    cudaGetSymbolAddress((void**)&p_h1,    g_h1);
    cudaGetSymbolAddress((void**)&p_as1,   g_as1);
    cudaGetSymbolAddress((void**)&p_ad1,   g_ad1);
    cudaGetSymbolAddress((void**)&p_emax1, g_emax1);
    cudaGetSymbolAddress((void**)&p_den1,  g_den1);
    cudaGetSymbolAddress((void**)&p_agg1,  g_agg1);
    cudaGetSymbolAddress((void**)&p_hin2,  g_hin2);
    cudaGetSymbolAddress((void**)&p_h2,    g_h2);
    cudaGetSymbolAddress((void**)&p_as2,   g_as2);
    cudaGetSymbolAddress((void**)&p_ad2,   g_ad2);
    cudaGetSymbolAddress((void**)&p_emax2, g_emax2);
    cudaGetSymbolAddress((void**)&p_den2,  g_den2);
    cudaGetSymbolAddress((void**)&p_agg2,  g_agg2);
    cudaGetSymbolAddress((void**)&p_imp,   g_imp);

    // zero accumulators (emax=0 encodes "below any real value"; every dst has
    // a self-loop so the max is always overwritten)
    cudaMemsetAsync(p_emax1, 0, (size_t)N * 2 * sizeof(unsigned));
    cudaMemsetAsync(p_den1,  0, (size_t)N * 2 * sizeof(float));
    cudaMemsetAsync(p_agg1,  0, (size_t)N * 64 * sizeof(float));
    cudaMemsetAsync(p_emax2, 0, (size_t)N * sizeof(unsigned));
    cudaMemsetAsync(p_den2,  0, (size_t)N * sizeof(float));
    cudaMemsetAsync(p_agg2,  0, (size_t)N * 32 * sizeof(float));

    detect_kernel<<<1, 32>>>((const int*)ei, in_sizes[1]);

    int Etot = E + N;
    int egrid = (Etot + 255) / 256;

    // ---- layer 1 (IN=64, H=2) ----
    {
        int grid = (N + 63) / 64;
        gemm_att_kernel<64, 2><<<grid, 256>>>(x, W1, as1w, ad1w, p_h1, p_as1, p_ad1, N);
    }
    edge_max_kernel<2><<<egrid, 256>>>(ei, E, N, p_as1, p_ad1, p_emax1);
    edge_sum_kernel<2><<<egrid, 256>>>(ei, E, N, p_as1, p_ad1, p_emax1, p_den1);
    edge_agg_kernel<2><<<egrid, 256>>>(ei, E, N, p_as1, p_ad1, p_emax1, p_den1, p_h1, p_agg1);
    finalize1_kernel<<<(N * 32 + 255) / 256, 256>>>(p_agg1, b1, p_hin2, N);

    // ---- layer 2 (IN=32, H=1) ----
    {
        int grid = (N + 127) / 128;
        gemm_att_kernel<32, 1><<<grid, 256>>>(p_hin2, W2, as2w, ad2w, p_h2, p_as2, p_ad2, N);
    }
    edge_max_kernel<1><<<egrid, 256>>>(ei, E, N, p_as2, p_ad2, p_emax2);
    edge_sum_kernel<1><<<egrid, 256>>>(ei, E, N, p_as2, p_ad2, p_emax2, p_den2);
    edge_agg_kernel<1><<<egrid, 256>>>(ei, E, N, p_as2, p_ad2, p_emax2, p_den2, p_h2, p_agg2);

    // ---- outputs: [embeds N*32][importance N][top5 idx] ----
    float* embeds_dst = (out_size >= N * 32) ? out : p_h2;
    float* imp_dst    = (out_size >= N * 33) ? (out + (size_t)N * 32) : nullptr;
    float* idx_dst    = (out_size >= N * 33 + 5) ? (out + (size_t)N * 33) : nullptr;

    finalize2_kernel<<<(N + 255) / 256, 256>>>(p_agg2, b2, embeds_dst, imp_dst, p_imp, N);
    topk_kernel<<<1, 256>>>(p_imp, N, idx_dst);
}

// round 3
// speedup vs baseline: 2.6557x; 2.6557x over previous
#include <cuda_runtime.h>
#include <math.h>

#define NN 100000
#define EE 3400000
#define NEG_SLOPE 0.2f

// ---------------- scratch (device globals; no allocations allowed) ----------
__device__ float g_h1[NN * 64];      // layer1 features [N, 2, 32]
__device__ float g_as1[NN * 2];
__device__ float g_ad1[NN * 2];
__device__ float g_hin2[NN * 32];    // relu(mean-heads + b1)
__device__ float g_h2[NN * 32];
__device__ float g_as2[NN];
__device__ float g_ad2[NN];
__device__ float g_imp[NN];
__device__ int   g_idx64;            // 1 if edge_index is int64, 0 if int32

// CSR by destination (shared by both layers)
__device__ int g_deg[NN];
__device__ int g_rowstart[NN + 1];
__device__ int g_cursor[NN];
__device__ int g_col[EE];

// top-k staging
#define TK_BLOCKS 128
__device__ float g_cand_v[TK_BLOCKS * 5];
__device__ int   g_cand_i[TK_BLOCKS * 5];

__device__ __forceinline__ float lrelu(float x) {
    return x > 0.f ? x : NEG_SLOPE * x;
}

// ------------------------- edge-index dtype detection -----------------------
__global__ void detect_kernel(const int* __restrict__ ei32, int nwords) {
    // If dtype is int64 (all values < 2^31), every odd 32-bit word is 0.
    int odd_nonzero = 0;
    int cnt = nwords < 512 ? nwords / 2 : 256;
    for (int i = threadIdx.x; i < cnt; i += 32)
        if (ei32[2 * i + 1] != 0) odd_nonzero = 1;
    odd_nonzero = __any_sync(0xFFFFFFFFu, odd_nonzero);
    if (threadIdx.x == 0) g_idx64 = odd_nonzero ? 0 : 1;
}

__device__ __forceinline__ void load_sd(const void* ei, int E, int i, int idx64,
                                        int& s, int& d) {
    if (idx64) {
        const long long* p = (const long long*)ei;
        s = (int)p[i]; d = (int)p[E + i];
    } else {
        const int* p = (const int*)ei;
        s = p[i]; d = p[E + i];
    }
}

// ------------------------------ CSR build -----------------------------------
__global__ void csr_count_kernel(const void* __restrict__ ei, int E) {
    int i = blockIdx.x * blockDim.x + threadIdx.x;
    if (i >= E) return;
    int idx64 = g_idx64;
    int d;
    if (idx64) d = (int)((const long long*)ei)[E + i];
    else       d = ((const int*)ei)[E + i];
    atomicAdd(&g_deg[d], 1);
}

__global__ void csr_scan_kernel(int N) {
    __shared__ int sums[1024];
    int t = threadIdx.x;
    int chunk = (N + 1023) >> 10;
    int b = t * chunk;
    int e = b + chunk; if (e > N) e = N;
    int s = 0;
    for (int i = b; i < e; ++i) s += g_deg[i];
    sums[t] = s;
    __syncthreads();
    for (int o = 1; o < 1024; o <<= 1) {
        int v = (t >= o) ? sums[t - o] : 0;
        __syncthreads();
        sums[t] += v;
        __syncthreads();
    }
    int pre = (t == 0) ? 0 : sums[t - 1];
    for (int i = b; i < e; ++i) {
        g_rowstart[i] = pre;
        g_cursor[i]   = pre;
        pre += g_deg[i];
    }
    if (t == 1023) g_rowstart[N] = sums[1023];
}

__global__ void csr_scatter_kernel(const void* __restrict__ ei, int E) {
    int i = blockIdx.x * blockDim.x + threadIdx.x;
    if (i >= E) return;
    int idx64 = g_idx64;
    int s, d;
    load_sd(ei, E, i, idx64, s, d);
    int pos = atomicAdd(&g_cursor[d], 1);
    g_col[pos] = s;
}

// --------------------- fused GEMM + attention coefficients ------------------
template<int IN, int H>
__global__ void gemm_att_kernel(const float* __restrict__ x,
                                const float* __restrict__ W,
                                const float* __restrict__ att_src,
                                const float* __restrict__ att_dst,
                                float* __restrict__ hout,
                                float* __restrict__ asrc,
                                float* __restrict__ adst,
                                int N) {
    constexpr int COLS  = H * 32;
    constexpr int RPI   = 256 / COLS;   // rows per iteration
    constexpr int ITERS = 16;

    __shared__ float Ws[IN * COLS];
    __shared__ float as_s[COLS];
    __shared__ float ad_s[COLS];
    __shared__ float xs[RPI][IN];

    int t = threadIdx.x;
    for (int i = t; i < IN * COLS; i += 256) Ws[i] = W[i];
    if (t < COLS) { as_s[t] = att_src[t]; ad_s[t] = att_dst[t]; }
    __syncthreads();

    int col  = t % COLS;
    int r    = t / COLS;
    int lane = t & 31;
    int head = col >> 5;
    long long row0 = (long long)blockIdx.x * (RPI * ITERS);

    for (int it = 0; it < ITERS; ++it) {
        long long rowbase = row0 + (long long)it * RPI;
        __syncthreads();
        for (int i = t; i < RPI * IN; i += 256) {
            int rr = i / IN, k = i % IN;
            long long row = rowbase + rr;
            xs[rr][k] = (row < N) ? x[row * IN + k] : 0.f;
        }
        __syncthreads();

        long long row = rowbase + r;
        float acc = 0.f;
        #pragma unroll
        for (int k = 0; k < IN; ++k) acc += xs[r][k] * Ws[k * COLS + col];

        float s1 = acc * as_s[col];
        float s2 = acc * ad_s[col];
        #pragma unroll
        for (int o = 16; o > 0; o >>= 1) {
            s1 += __shfl_xor_sync(0xFFFFFFFFu, s1, o);
            s2 += __shfl_xor_sync(0xFFFFFFFFu, s2, o);
        }
        if (row < N) {
            hout[row * COLS + col] = acc;
            if (lane == 0) {
                asrc[row * H + head] = s1;
                adst[row * H + head] = s2;
            }
        }
    }
}

// ------------- fused online-softmax aggregation (warp per dst node) ---------
// lane = feature dim. Self-loop handled implicitly. H=2: epilogue does
// head-mean + b + relu; H=1: epilogue does +b, writes embeds and L2 norm.
template<int H>
__global__ void gat_agg_kernel(const float* __restrict__ asrc,
                               const float* __restrict__ adst,
                               const float* __restrict__ hfeat,
                               const float* __restrict__ bias,
                               float* __restrict__ outv,
                               float* __restrict__ imp_a,   // H==1 only
                               float* __restrict__ imp_b,   // may be null
                               int N) {
    __shared__ int   s_idx[8][32];
    __shared__ float s_w[8][H][32];

    int warp_id = (blockIdx.x * blockDim.x + threadIdx.x) >> 5;
    int lane  = threadIdx.x & 31;
    int wslot = (threadIdx.x >> 5) & 7;
    if (warp_id >= N) return;
    int d = warp_id;

    float ad[H], m[H], den[H], acc[H];
    #pragma unroll
    for (int h = 0; h < H; ++h) {
        ad[h] = adst[d * H + h];
        float e_self = lrelu(asrc[d * H + h] + ad[h]);
        m[h]   = e_self;
        den[h] = (lane == 0) ? 1.f : 0.f;   // self weight exp(0)=1 at m=e_self
        acc[h] = hfeat[((size_t)d * H + h) * 32 + lane];
    }

    int beg = g_rowstart[d], end = g_rowstart[d + 1];
    for (int base = beg; base < end; base += 32) {
        int j = base + lane;
        bool valid = j < end;
        int s = valid ? g_col[j] : 0;
        s_idx[wslot][lane] = s;

        #pragma unroll
        for (int h = 0; h < H; ++h) {
            float e = valid ? lrelu(asrc[s * H + h] + ad[h]) : -3.0e38f;
            float cm = e;
            #pragma unroll
            for (int o = 16; o; o >>= 1)
                cm = fmaxf(cm, __shfl_xor_sync(0xFFFFFFFFu, cm, o));
            float newm = fmaxf(m[h], cm);
            float rs = __expf(m[h] - newm);
            acc[h] *= rs; den[h] *= rs; m[h] = newm;
            float w = valid ? __expf(e - newm) : 0.f;
            den[h] += w;
            s_w[wslot][h][lane] = w;
        }
        __syncwarp();

        int cnt = end - base; if (cnt > 32) cnt = 32;
        if (cnt == 32) {
            #pragma unroll 8
            for (int k = 0; k < 32; ++k) {
                int sk = s_idx[wslot][k];
                #pragma unroll
                for (int h = 0; h < H; ++h)
                    acc[h] += s_w[wslot][h][k] *
                              hfeat[((size_t)sk * H + h) * 32 + lane];
            }
        } else {
            for (int k = 0; k < cnt; ++k) {
                int sk = s_idx[wslot][k];
                #pragma unroll
                for (int h = 0; h < H; ++h)
                    acc[h] += s_w[wslot][h][k] *
                              hfeat[((size_t)sk * H + h) * 32 + lane];
            }
        }
        __syncwarp();
    }

    #pragma unroll
    for (int h = 0; h < H; ++h) {
        float dsum = den[h];
        #pragma unroll
        for (int o = 16; o; o >>= 1)
            dsum += __shfl_xor_sync(0xFFFFFFFFu, dsum, o);
        acc[h] = acc[h] / (dsum + 1e-16f);
    }

    if (H == 2) {
        float v = 0.5f * (acc[0] + acc[1]) + bias[lane];
        outv[(size_t)d * 32 + lane] = fmaxf(v, 0.f);
    } else {
        float v = acc[0] + bias[lane];
        outv[(size_t)d * 32 + lane] = v;
        float ss = v * v;
        #pragma unroll
        for (int o = 16; o; o >>= 1)
            ss += __shfl_xor_sync(0xFFFFFFFFu, ss, o);
        if (lane == 0) {
            float nm = sqrtf(ss);
            imp_a[d] = nm;
            if (imp_b) imp_b[d] = nm;
        }
    }
}

// --------------------------------- top-k ------------------------------------
__global__ void topk_stage1_kernel(const float* __restrict__ imp, int N) {
    __shared__ float bv[256];
    __shared__ int   bi[256];
    __shared__ int   chosen[5];
    int chunk = (N + TK_BLOCKS - 1) / TK_BLOCKS;
    int lo = blockIdx.x * chunk;
    int hi = lo + chunk; if (hi > N) hi = N;
    for (int r = 0; r < 5; ++r) {
        float best = -1e30f; int besti = 0x7FFFFFFF;
        for (int i = lo + threadIdx.x; i < hi; i += 256) {
            bool skip = false;
            for (int c = 0; c < r; ++c) if (chosen[c] == i) skip = true;
            if (skip) continue;
            float v = imp[i];
            if (v > best || (v == best && i < besti)) { best = v; besti = i; }
        }
        bv[threadIdx.x] = best;
        bi[threadIdx.x] = besti;
        __syncthreads();
        if (threadIdx.x == 0) {
            float B = -1e30f; int BI = 0x7FFFFFFF;
            for (int t = 0; t < 256; ++t)
                if (bv[t] > B || (bv[t] == B && bi[t] < BI)) { B = bv[t]; BI = bi[t]; }
            chosen[r] = BI;
            g_cand_v[blockIdx.x * 5 + r] = B;
            g_cand_i[blockIdx.x * 5 + r] = BI;
        }
        __syncthreads();
    }
}

__global__ void topk_stage2_kernel(float* __restrict__ out_idx) {
    __shared__ float bv[256];
    __shared__ int   bi[256];
    __shared__ int   chosen[5];
    const int M = TK_BLOCKS * 5;
    for (int r = 0; r < 5; ++r) {
        float best = -1e30f; int besti = 0x7FFFFFFF;
        for (int i = threadIdx.x; i < M; i += 256) {
            int gi = g_cand_i[i];
            bool skip = false;
            for (int c = 0; c < r; ++c) if (chosen[c] == gi) skip = true;
            if (skip) continue;
            float v = g_cand_v[i];
            if (v > best || (v == best && gi < besti)) { best = v; besti = gi; }
        }
        bv[threadIdx.x] = best;
        bi[threadIdx.x] = besti;
        __syncthreads();
        if (threadIdx.x == 0) {
            float B = -1e30f; int BI = 0x7FFFFFFF;
            for (int t = 0; t < 256; ++t)
                if (bv[t] > B || (bv[t] == B && bi[t] < BI)) { B = bv[t]; BI = bi[t]; }
            chosen[r] = BI;
            if (out_idx) out_idx[r] = (float)BI;
        }
        __syncthreads();
    }
}

// --------------------------------- launch -----------------------------------
extern "C" void kernel_launch(void* const* d_in, const int* in_sizes, int n_in,
                              void* d_out, int out_size) {
    const float* x    = (const float*)d_in[0];
    const void*  ei   = d_in[1];
    const float* W1   = (const float*)d_in[2];
    const float* as1w = (const float*)d_in[3];
    const float* ad1w = (const float*)d_in[4];
    const float* b1   = (const float*)d_in[5];
    const float* W2   = (const float*)d_in[6];
    const float* as2w = (const float*)d_in[7];
    const float* ad2w = (const float*)d_in[8];
    const float* b2   = (const float*)d_in[9];
    float* out = (float*)d_out;

    int N = in_sizes[0] / 64;
    int E = in_sizes[1] / 2;
    if (N > NN) N = NN;
    if (E > EE) E = EE;

    float *p_h1, *p_as1, *p_ad1, *p_hin2, *p_h2, *p_as2, *p_ad2, *p_imp;
    int *p_deg;
    cudaGetSymbolAddress((void**)&p_h1,   g_h1);
    cudaGetSymbolAddress((void**)&p_as1,  g_as1);
    cudaGetSymbolAddress((void**)&p_ad1,  g_ad1);
    cudaGetSymbolAddress((void**)&p_hin2, g_hin2);
    cudaGetSymbolAddress((void**)&p_h2,   g_h2);
    cudaGetSymbolAddress((void**)&p_as2,  g_as2);
    cudaGetSymbolAddress((void**)&p_ad2,  g_ad2);
    cudaGetSymbolAddress((void**)&p_imp,  g_imp);
    cudaGetSymbolAddress((void**)&p_deg,  g_deg);

    cudaMemsetAsync(p_deg, 0, (size_t)N * sizeof(int));
    detect_kernel<<<1, 32>>>((const int*)ei, in_sizes[1]);

    // ---- CSR build (dst shared by both layers) ----
    int egrid = (E + 255) / 256;
    csr_count_kernel<<<egrid, 256>>>(ei, E);
    csr_scan_kernel<<<1, 1024>>>(N);
    csr_scatter_kernel<<<egrid, 256>>>(ei, E);

    // ---- layer 1 (IN=64, H=2) ----
    gemm_att_kernel<64, 2><<<(N + 63) / 64, 256>>>(x, W1, as1w, ad1w,
                                                   p_h1, p_as1, p_ad1, N);
    gat_agg_kernel<2><<<(N + 7) / 8, 256>>>(p_as1, p_ad1, p_h1, b1,
                                            p_hin2, nullptr, nullptr, N);

    // ---- layer 2 (IN=32, H=1) ----
    gemm_att_kernel<32, 1><<<(N + 127) / 128, 256>>>(p_hin2, W2, as2w, ad2w,
                                                     p_h2, p_as2, p_ad2, N);

    float* embeds_dst = (out_size >= N * 32) ? out : p_h2;
    float* imp_dst    = (out_size >= N * 33) ? (out + (size_t)N * 32) : nullptr;
    float* idx_dst    = (out_size >= N * 33 + 5) ? (out + (size_t)N * 33) : nullptr;

    gat_agg_kernel<1><<<(N + 7) / 8, 256>>>(p_as2, p_ad2, p_h2, b2,
                                            embeds_dst, p_imp, imp_dst, N);

    // ---- top-k (two-stage) ----
    topk_stage1_kernel<<<TK_BLOCKS, 256>>>(p_imp, N);
    topk_stage2_kernel<<<1, 256>>>(idx_dst);
}